// round 2
// baseline (speedup 1.0000x reference)
#include <cuda_runtime.h>
#include <cstdint>

// x: (2, 3, 256, 256, 256) float32 ; out: (2, 256, 256, 256) float32
//
// out[b,z,y,i] = 0.5 * ( u[b,z,y,(i+1)&255] - u[b,z,y,(i-1)&255]
//                      + v[b,z,(y+1)&255,i] - v[b,z,(y-1)&255,i]
//                      + w[b,(z+1)&255,(y+1)&255,i] - w[b,(z-1)&255,(y-1)&255,i] )
//
// Each thread processes TWO float4s of the same row: columns [i0,i0+4) and
// [i0+128,i0+132). Warp lanes cover consecutive i0, so every LDG.128 /
// STG.128 is a fully-coalesced 512B warp transaction.

#define DIM 256
#define DIMM 255
#define VOL (DIM * DIM * DIM)

__global__ __launch_bounds__(256) void calc_divergence_kernel(
    const float* __restrict__ x, float* __restrict__ out)
{
    const uint32_t idx = blockIdx.x * blockDim.x + threadIdx.x;
    // decompose: [b:1][z:8][y:8][xh:5]
    const uint32_t xh = idx & 31;
    const uint32_t y  = (idx >> 5) & DIMM;
    const uint32_t z  = (idx >> 13) & DIMM;
    const uint32_t b  = idx >> 21;

    const uint32_t i0 = xh << 2;        // [0,124]
    const uint32_t i1 = i0 + 128;       // [128,252]

    const float* u = x + (size_t)(b * 3 + 0) * VOL;
    const float* v = x + (size_t)(b * 3 + 1) * VOL;
    const float* w = x + (size_t)(b * 3 + 2) * VOL;

    const uint32_t yp = (y + 1) & DIMM;
    const uint32_t ym = (y - 1) & DIMM;
    const uint32_t zp = (z + 1) & DIMM;
    const uint32_t zm = (z - 1) & DIMM;

    const size_t rowc  = ((size_t)z  * DIM + y ) * DIM;
    const size_t rowvp = ((size_t)z  * DIM + yp) * DIM;
    const size_t rowvm = ((size_t)z  * DIM + ym) * DIM;
    const size_t rowwp = ((size_t)zp * DIM + yp) * DIM;
    const size_t rowwm = ((size_t)zm * DIM + ym) * DIM;

    const float* urow = u + rowc;

    // ---- issue all global loads up front (max MLP) ----
    const float4 uc0 = *reinterpret_cast<const float4*>(urow + i0);
    const float4 uc1 = *reinterpret_cast<const float4*>(urow + i1);
    const float4 vp0 = *reinterpret_cast<const float4*>(v + rowvp + i0);
    const float4 vp1 = *reinterpret_cast<const float4*>(v + rowvp + i1);
    const float4 vm0 = *reinterpret_cast<const float4*>(v + rowvm + i0);
    const float4 vm1 = *reinterpret_cast<const float4*>(v + rowvm + i1);
    const float4 wp0 = *reinterpret_cast<const float4*>(w + rowwp + i0);
    const float4 wp1 = *reinterpret_cast<const float4*>(w + rowwp + i1);
    const float4 wm0 = *reinterpret_cast<const float4*>(w + rowwm + i0);
    const float4 wm1 = *reinterpret_cast<const float4*>(w + rowwm + i1);

    // u edge scalars (L1-hit: same cachelines as neighbors' float4 loads)
    const float ul0 = urow[(i0 + DIMM) & DIMM];  // i0-1 mod 256 (wraps only at i0==0)
    const float ur0 = urow[i0 + 4];              // [4,128] — no wrap
    const float ul1 = urow[i1 - 1];              // [127,251] — no wrap
    const float ur1 = urow[(i1 + 4) & DIMM];     // wraps only at i1==252

    float4 r0, r1;
    r0.x = 0.5f * ((uc0.y - ul0)   + (vp0.x - vm0.x) + (wp0.x - wm0.x));
    r0.y = 0.5f * ((uc0.z - uc0.x) + (vp0.y - vm0.y) + (wp0.y - wm0.y));
    r0.z = 0.5f * ((uc0.w - uc0.y) + (vp0.z - vm0.z) + (wp0.z - wm0.z));
    r0.w = 0.5f * ((ur0   - uc0.z) + (vp0.w - vm0.w) + (wp0.w - wm0.w));

    r1.x = 0.5f * ((uc1.y - ul1)   + (vp1.x - vm1.x) + (wp1.x - wm1.x));
    r1.y = 0.5f * ((uc1.z - uc1.x) + (vp1.y - vm1.y) + (wp1.y - wm1.y));
    r1.z = 0.5f * ((uc1.w - uc1.y) + (vp1.z - vm1.z) + (wp1.z - wm1.z));
    r1.w = 0.5f * ((ur1   - uc1.z) + (vp1.w - vm1.w) + (wp1.w - wm1.w));

    float* orow = out + ((size_t)(b * DIM + z) * DIM + y) * DIM;
    // streaming stores: output is never re-read, keep it out of L2's reuse set
    __stcs(reinterpret_cast<float4*>(orow + i0), r0);
    __stcs(reinterpret_cast<float4*>(orow + i1), r1);
}

extern "C" void kernel_launch(void* const* d_in, const int* in_sizes, int n_in,
                              void* d_out, int out_size)
{
    const float* x = (const float*)d_in[0];
    float* out = (float*)d_out;

    const uint32_t total_threads = 2u * DIM * DIM * 32;   // 4,194,304
    const uint32_t threads = 256;
    const uint32_t blocks = total_threads / threads;      // 16,384

    calc_divergence_kernel<<<blocks, threads>>>(x, out);
}

// round 3
// speedup vs baseline: 1.0440x; 1.0440x over previous
#include <cuda_runtime.h>
#include <cstdint>

// x: (2, 3, 256, 256, 256) float32 ; out: (2, 256, 256, 256) float32
//
// out[b,z,y,i] = 0.5 * ( u[b,z,y,(i+1)&255] - u[b,z,y,(i-1)&255]
//                      + v[b,z,(y+1)&255,i] - v[b,z,(y-1)&255,i]
//                      + w[b,(z+1)&255,(y+1)&255,i] - w[b,(z-1)&255,(y-1)&255,i] )
//
// One thread per float4 of output (8,388,608 threads) — R1 shape, which
// measured DRAM=87.3% / 6.9 TB/s. Streaming stores added.

#define DIM 256
#define DIMM 255
#define Q 64
#define VOL (DIM * DIM * DIM)

__global__ __launch_bounds__(256) void calc_divergence_kernel(
    const float* __restrict__ x, float* __restrict__ out)
{
    const uint32_t idx = blockIdx.x * blockDim.x + threadIdx.x;
    // decompose: [b:1][z:8][y:8][xq:6]
    const uint32_t xq = idx & (Q - 1);
    const uint32_t y  = (idx >> 6) & DIMM;
    const uint32_t z  = (idx >> 14) & DIMM;
    const uint32_t b  = idx >> 22;

    const uint32_t i0 = xq << 2;

    const float* u = x + (size_t)(b * 3 + 0) * VOL;
    const float* v = x + (size_t)(b * 3 + 1) * VOL;
    const float* w = x + (size_t)(b * 3 + 2) * VOL;

    const uint32_t yp = (y + 1) & DIMM;
    const uint32_t ym = (y - 1) & DIMM;
    const uint32_t zp = (z + 1) & DIMM;
    const uint32_t zm = (z - 1) & DIMM;

    // ---- u: x-direction central difference (periodic) ----
    const float* urow = u + ((size_t)z * DIM + y) * DIM;
    const float4 uc = *reinterpret_cast<const float4*>(urow + i0);
    const float  ul = urow[(i0 - 1) & DIMM];
    const float  ur = urow[(i0 + 4) & DIMM];

    float4 du;
    du.x = uc.y - ul;
    du.y = uc.z - uc.x;
    du.z = uc.w - uc.y;
    du.w = ur   - uc.z;

    // ---- v: y-direction central difference ----
    const float4 vp = *reinterpret_cast<const float4*>(v + ((size_t)z * DIM + yp) * DIM + i0);
    const float4 vm = *reinterpret_cast<const float4*>(v + ((size_t)z * DIM + ym) * DIM + i0);

    // ---- w: diagonal (z,y) central difference ----
    const float4 wp = *reinterpret_cast<const float4*>(w + ((size_t)zp * DIM + yp) * DIM + i0);
    const float4 wm = *reinterpret_cast<const float4*>(w + ((size_t)zm * DIM + ym) * DIM + i0);

    float4 r;
    r.x = 0.5f * (du.x + (vp.x - vm.x) + (wp.x - wm.x));
    r.y = 0.5f * (du.y + (vp.y - vm.y) + (wp.y - wm.y));
    r.z = 0.5f * (du.z + (vp.z - vm.z) + (wp.z - wm.z));
    r.w = 0.5f * (du.w + (vp.w - vm.w) + (wp.w - wm.w));

    // streaming store: output is never re-read — evict-first, keep L2 for
    // the v/w neighbor-row reuse window
    __stcs(reinterpret_cast<float4*>(out + ((size_t)(b * DIM + z) * DIM + y) * DIM + i0), r);
}

extern "C" void kernel_launch(void* const* d_in, const int* in_sizes, int n_in,
                              void* d_out, int out_size)
{
    const float* x = (const float*)d_in[0];
    float* out = (float*)d_out;

    const uint32_t total_f4 = 2u * DIM * DIM * Q;   // 8,388,608
    const uint32_t threads = 256;
    const uint32_t blocks = total_f4 / threads;     // 32,768

    calc_divergence_kernel<<<blocks, threads>>>(x, out);
}